// round 12
// baseline (speedup 1.0000x reference)
#include <cuda_runtime.h>
#include <math.h>

#define BB   32
#define LL   1024
#define DG   1024
#define HH   1024
#define OUTW 2048
#define BL   (BB * LL)          // 32768 rows
#define NGROUPS 128             // (bg,lt) gate groups

__device__ float        g_part[4 * BL];   // split-K partials
__device__ float        g_gate[BL];       // final sigmoid gate
__device__ unsigned int g_cnt[NGROUPS];   // self-resetting split-K arrival counters
__device__ int          g_done;           // gate-completion counter (reset each replay)

__global__ void reset_kernel() { g_done = 0; }

// ---------------------------------------------------------------------------
// Gate: split-K-4 GEMM + fixup (R10 form, passed). PDL trigger at ENTRY so the
// stream kernel co-schedules; data readiness is signaled via g_done (release).
// Grid 512 = (32 lt) x (4 bg) x (4 hq), 512 threads.
// ---------------------------------------------------------------------------
__global__ __launch_bounds__(512, 2)
void gate_kernel(const float* __restrict__ query,
                 const float* __restrict__ W,
                 const float* __restrict__ bias)
{
    __shared__ float sq[8 * 256];
    __shared__ float red[16][8][32];
    __shared__ int   s_last;

    const int tid = threadIdx.x;
    if (tid == 0) cudaTriggerProgrammaticLaunchCompletion();

    const int warp = tid >> 5;
    const int lane = tid & 31;
    const int bid  = blockIdx.x;
    const int lt   = bid & 31;
    const int bg   = (bid >> 5) & 3;
    const int hq   = bid >> 7;

    {
        const int b = tid >> 6;
        const int j = tid & 63;
        ((float4*)sq)[b * 64 + j] =
            __ldg((const float4*)query + (bg * 8 + b) * (HH / 4) + hq * 64 + j);
    }
    __syncthreads();

    const int l  = lt * 32 + lane;
    const int h0 = hq * 256 + warp * 16;

    float w[16];
    #pragma unroll
    for (int j = 0; j < 16; ++j)
        w[j] = __ldg(&W[(h0 + j) * LL + l]);

    float acc[8];
    #pragma unroll
    for (int b = 0; b < 8; ++b) acc[b] = 0.f;

    #pragma unroll
    for (int b = 0; b < 8; ++b) {
        const float* qb = sq + b * 256 + warp * 16;
        #pragma unroll
        for (int j = 0; j < 16; ++j)
            acc[b] = fmaf(qb[j], w[j], acc[b]);
    }

    #pragma unroll
    for (int b = 0; b < 8; ++b) red[warp][b][lane] = acc[b];
    __syncthreads();

    if (tid < 256) {
        const int b = tid >> 5;
        float s = 0.f;
        #pragma unroll
        for (int w2 = 0; w2 < 16; ++w2) s += red[w2][b][lane];
        g_part[hq * BL + (bg * 8 + b) * LL + l] = s;
        __threadfence();
    }
    __syncthreads();

    if (tid == 0) {
        unsigned old = atomicInc(&g_cnt[(bg << 5) | lt], 3u);  // wraps 3 -> 0
        s_last = (old == 3u);
        if (s_last) __threadfence();
    }
    __syncthreads();

    if (s_last) {
        if (tid < 256) {
            const int b   = tid >> 5;
            const int idx = (bg * 8 + b) * LL + l;
            float s = __ldg(&bias[l])
                    + __ldcg(&g_part[0 * BL + idx])
                    + __ldcg(&g_part[1 * BL + idx])
                    + __ldcg(&g_part[2 * BL + idx])
                    + __ldcg(&g_part[3 * BL + idx]);
            g_gate[idx] = 1.0f / (1.0f + __expf(-s));
        }
        __syncthreads();
        if (tid == 0) {
            __threadfence();               // release g_gate before counting done
            atomicAdd(&g_done, 1);
        }
    }
}

// ---------------------------------------------------------------------------
// Stream: R2's proven form + PDL co-start. Loads first (gate-independent),
// then spin-acquire on g_done, then gate-scale + store.
// ---------------------------------------------------------------------------
__global__ __launch_bounds__(256, 8)
void stream_kernel(const float4* __restrict__ graph,
                   const float4* __restrict__ query,
                   float4* __restrict__ out)
{
    const int bl  = blockIdx.x;
    const int b   = bl >> 10;
    const int tid = threadIdx.x;

    // Gate-independent long-latency loads first
    const float4 v = __ldcs(&graph[(long long)bl * (DG / 4) + tid]);
    const float4 q = __ldg(&query[b * (HH / 4) + tid]);

    // Acquire: wait until all 128 gate groups have published g_gate
    if (tid == 0) {
        while (*((volatile int*)&g_done) < NGROUPS) __nanosleep(32);
    }
    __syncthreads();
    __threadfence();                       // acquire ordering for g_gate reads

    const float g = __ldcg(&g_gate[bl]);

    float4* o = out + (long long)bl * (OUTW / 4);
    __stcs(&o[tid],            make_float4(v.x * g, v.y * g, v.z * g, v.w * g));
    __stcs(&o[(DG / 4) + tid], q);
}

extern "C" void kernel_launch(void* const* d_in, const int* in_sizes, int n_in,
                              void* d_out, int out_size)
{
    const float* graph = (const float*)d_in[0];
    const float* query = (const float*)d_in[1];
    const float* W     = (const float*)d_in[2];
    const float* bias  = (const float*)d_in[3];
    float* out = (float*)d_out;

    reset_kernel<<<1, 1>>>();
    gate_kernel<<<512, 512>>>(query, W, bias);

    cudaLaunchConfig_t cfg = {};
    cfg.gridDim  = dim3(BL, 1, 1);
    cfg.blockDim = dim3(256, 1, 1);
    cfg.dynamicSmemBytes = 0;
    cfg.stream = 0;
    cudaLaunchAttribute attr[1];
    attr[0].id = cudaLaunchAttributeProgrammaticStreamSerialization;
    attr[0].val.programmaticStreamSerializationAllowed = 1;
    cfg.attrs = attr;
    cfg.numAttrs = 1;

    cudaLaunchKernelEx(&cfg, stream_kernel,
                       (const float4*)graph, (const float4*)query,
                       (float4*)out);

    (void)in_sizes; (void)n_in; (void)out_size;
}

// round 14
// speedup vs baseline: 1.1198x; 1.1198x over previous
#include <cuda_runtime.h>
#include <math.h>

#define BB   32
#define LL   1024
#define DG   1024
#define HH   1024
#define OUTW 2048
#define BL   (BB * LL)          // 32768 rows

// Split-K partials, packed per row: g_part4[bl] = {hq0, hq1, hq2, hq3}
__device__ float4 g_part4[BL];

// ---------------------------------------------------------------------------
// Gate partials: split-K-4 GEMM, no fixup.
// Grid 512 = (32 l-tiles) x (4 batch groups) x (4 h-quarters), 512 threads.
// Each block: 8 batches x 32 l x 256 h. All 16 W loads per warp issued
// up-front (MLP=16). Writes raw partial dot products (pre-bias/sigmoid).
// ---------------------------------------------------------------------------
__global__ __launch_bounds__(512, 2)
void gate_partial(const float* __restrict__ query,
                  const float* __restrict__ W)
{
    __shared__ float sq[8 * 256];         // 8 KiB query slice
    __shared__ float red[16][8][32];      // 16 KiB

    const int tid  = threadIdx.x;
    const int warp = tid >> 5;
    const int lane = tid & 31;
    const int bid  = blockIdx.x;
    const int lt   = bid & 31;            // l-tile
    const int bg   = (bid >> 5) & 3;      // batch group
    const int hq   = bid >> 7;            // h-quarter

    // Stage 8 x 256 query slice (512 float4, one per thread)
    {
        const int b = tid >> 6;
        const int j = tid & 63;
        ((float4*)sq)[b * 64 + j] =
            __ldg((const float4*)query + (bg * 8 + b) * (HH / 4) + hq * 64 + j);
    }
    __syncthreads();

    const int l  = lt * 32 + lane;
    const int h0 = hq * 256 + warp * 16;

    // All 16 W loads up-front: MLP=16
    float w[16];
    #pragma unroll
    for (int j = 0; j < 16; ++j)
        w[j] = __ldg(&W[(h0 + j) * LL + l]);

    float acc[8];
    #pragma unroll
    for (int b = 0; b < 8; ++b) acc[b] = 0.f;

    #pragma unroll
    for (int b = 0; b < 8; ++b) {
        const float* qb = sq + b * 256 + warp * 16;
        #pragma unroll
        for (int j = 0; j < 16; ++j)
            acc[b] = fmaf(qb[j], w[j], acc[b]);
    }

    #pragma unroll
    for (int b = 0; b < 8; ++b) red[warp][b][lane] = acc[b];
    __syncthreads();

    if (tid < 256) {
        const int b = tid >> 5;
        float s = 0.f;
        #pragma unroll
        for (int w2 = 0; w2 < 16; ++w2) s += red[w2][b][lane];
        // packed layout: component hq of row (bg*8+b)*LL + l
        ((float*)&g_part4[(bg * 8 + b) * LL + l])[hq] = s;
    }
}

// ---------------------------------------------------------------------------
// Stream: R2's pristine form + barrier-free redundant gate finalize.
// One block per (b,l) row, 256 threads. Every thread computes
// g = sigmoid(bias[l] + sum(partials)) itself from broadcast loads —
// no smem, no __syncthreads, finalize hides under the DRAM load shadow.
// ---------------------------------------------------------------------------
__global__ __launch_bounds__(256, 8)
void stream_kernel(const float4* __restrict__ graph,
                   const float4* __restrict__ query,
                   const float*  __restrict__ bias,
                   float4* __restrict__ out)
{
    const int bl  = blockIdx.x;           // b*LL + l
    const int b   = bl >> 10;
    const int l   = bl & 1023;
    const int tid = threadIdx.x;

    // All loads independent, issued together (MLP=4 long + 2 broadcast)
    const float4 v = __ldcs(&graph[(long long)bl * (DG / 4) + tid]);
    const float4 q = __ldg(&query[b * (HH / 4) + tid]);
    const float4 p = __ldg(&g_part4[bl]);         // warp-broadcast, 1 sector
    const float  bi = __ldg(&bias[l]);            // warp-broadcast

    const float s = bi + ((p.x + p.y) + (p.z + p.w));
    const float g = 1.0f / (1.0f + __expf(-s));

    float4* o = out + (long long)bl * (OUTW / 4);
    __stcs(&o[tid],            make_float4(v.x * g, v.y * g, v.z * g, v.w * g));
    __stcs(&o[(DG / 4) + tid], q);
}

extern "C" void kernel_launch(void* const* d_in, const int* in_sizes, int n_in,
                              void* d_out, int out_size)
{
    const float* graph = (const float*)d_in[0];
    const float* query = (const float*)d_in[1];
    const float* W     = (const float*)d_in[2];
    const float* bias  = (const float*)d_in[3];
    float* out = (float*)d_out;

    gate_partial<<<512, 512>>>(query, W);
    stream_kernel<<<BL, 256>>>((const float4*)graph,
                               (const float4*)query,
                               bias,
                               (float4*)out);

    (void)in_sizes; (void)n_in; (void)out_size;
}

// round 15
// speedup vs baseline: 1.1496x; 1.0266x over previous
#include <cuda_runtime.h>
#include <math.h>

#define BB   32
#define LL   1024
#define DG   1024
#define HH   1024
#define OUTW 2048
#define BL   (BB * LL)          // 32768 rows

// Split-K partials, packed per row: g_part4[bl] = {hq0, hq1, hq2, hq3}
__device__ float4 g_part4[BL];

// ---------------------------------------------------------------------------
// Gate partials: split-K-4 GEMM (R14 form, proven).
// Grid 512 = (32 lt) x (4 bg) x (4 hq), 512 threads. MLP=16 W loads.
// NO explicit PDL trigger -> implicit trigger at kernel completion, which
// guarantees the secondary's cudaGridDependencySynchronize() sees all writes.
// ---------------------------------------------------------------------------
__global__ __launch_bounds__(512, 2)
void gate_partial(const float* __restrict__ query,
                  const float* __restrict__ W)
{
    __shared__ float sq[8 * 256];         // 8 KiB query slice
    __shared__ float red[16][8][32];      // 16 KiB

    const int tid  = threadIdx.x;
    const int warp = tid >> 5;
    const int lane = tid & 31;
    const int bid  = blockIdx.x;
    const int lt   = bid & 31;            // l-tile
    const int bg   = (bid >> 5) & 3;      // batch group
    const int hq   = bid >> 7;            // h-quarter

    {
        const int b = tid >> 6;
        const int j = tid & 63;
        ((float4*)sq)[b * 64 + j] =
            __ldg((const float4*)query + (bg * 8 + b) * (HH / 4) + hq * 64 + j);
    }
    __syncthreads();

    const int l  = lt * 32 + lane;
    const int h0 = hq * 256 + warp * 16;

    float w[16];
    #pragma unroll
    for (int j = 0; j < 16; ++j)
        w[j] = __ldg(&W[(h0 + j) * LL + l]);

    float acc[8];
    #pragma unroll
    for (int b = 0; b < 8; ++b) acc[b] = 0.f;

    #pragma unroll
    for (int b = 0; b < 8; ++b) {
        const float* qb = sq + b * 256 + warp * 16;
        #pragma unroll
        for (int j = 0; j < 16; ++j)
            acc[b] = fmaf(qb[j], w[j], acc[b]);
    }

    #pragma unroll
    for (int b = 0; b < 8; ++b) red[warp][b][lane] = acc[b];
    __syncthreads();

    if (tid < 256) {
        const int b = tid >> 5;
        float s = 0.f;
        #pragma unroll
        for (int w2 = 0; w2 < 16; ++w2) s += red[w2][b][lane];
        ((float*)&g_part4[(bg * 8 + b) * LL + l])[hq] = s;
    }
}

// ---------------------------------------------------------------------------
// Stream: R14's proven form (pristine R2 + barrier-free redundant finalize),
// launched as a PDL secondary. The grid-dependency sync sits AFTER the
// gate-independent loads; it waits for gate_partial COMPLETION (implicit
// trigger), so g_part4 is fully visible when read.
// ---------------------------------------------------------------------------
__global__ __launch_bounds__(256, 8)
void stream_kernel(const float4* __restrict__ graph,
                   const float4* __restrict__ query,
                   const float*  __restrict__ bias,
                   float4* __restrict__ out)
{
    const int bl  = blockIdx.x;           // b*LL + l
    const int b   = bl >> 10;
    const int l   = bl & 1023;
    const int tid = threadIdx.x;

    // Gate-independent long-latency loads first
    const float4 v = __ldcs(&graph[(long long)bl * (DG / 4) + tid]);
    const float4 q = __ldg(&query[b * (HH / 4) + tid]);
    const float  bi = __ldg(&bias[l]);    // warp-broadcast, gate-independent

    // Wait for gate_partial to COMPLETE (implicit trigger at completion
    // guarantees visibility of g_part4).
    cudaGridDependencySynchronize();

    const float4 p = __ldg(&g_part4[bl]); // warp-broadcast, 1 sector
    const float s = bi + ((p.x + p.y) + (p.z + p.w));
    const float g = 1.0f / (1.0f + __expf(-s));

    float4* o = out + (long long)bl * (OUTW / 4);
    __stcs(&o[tid],            make_float4(v.x * g, v.y * g, v.z * g, v.w * g));
    __stcs(&o[(DG / 4) + tid], q);
}

extern "C" void kernel_launch(void* const* d_in, const int* in_sizes, int n_in,
                              void* d_out, int out_size)
{
    const float* graph = (const float*)d_in[0];
    const float* query = (const float*)d_in[1];
    const float* W     = (const float*)d_in[2];
    const float* bias  = (const float*)d_in[3];
    float* out = (float*)d_out;

    gate_partial<<<512, 512>>>(query, W);

    // PDL secondary: launch setup overlaps gate_partial execution.
    cudaLaunchConfig_t cfg = {};
    cfg.gridDim  = dim3(BL, 1, 1);
    cfg.blockDim = dim3(256, 1, 1);
    cfg.dynamicSmemBytes = 0;
    cfg.stream = 0;
    cudaLaunchAttribute attr[1];
    attr[0].id = cudaLaunchAttributeProgrammaticStreamSerialization;
    attr[0].val.programmaticStreamSerializationAllowed = 1;
    cfg.attrs = attr;
    cfg.numAttrs = 1;

    cudaLaunchKernelEx(&cfg, stream_kernel,
                       (const float4*)graph, (const float4*)query,
                       bias, (float4*)out);

    (void)in_sizes; (void)n_in; (void)out_size;
}